// round 14
// baseline (speedup 1.0000x reference)
#include <cuda_runtime.h>
#include <cuda_bf16.h>
#include <mma.h>
#include <cstdint>
#include <math.h>

using namespace nvcuda;

// ---------------- problem constants ----------------
#define N_EMBD   1024
#define D_INNER  2048
#define D_STATE  64
#define N_HEADS  32
#define HEAD_DIM 64
#define D_CONV   4
#define SEQ      512
#define PROJ     4256          // 2*D_INNER + N_HEADS + 2*N_GROUPS*D_STATE
#define COL_GATE 0
#define COL_SSM  2048
#define AUX_COL0 4096          // dt(32) | B(64) | C(64) live in fp32 aux
#define AUX_W    160

// ---------------- scratch (no allocation allowed) ----------------
__device__ __nv_bfloat16 g_xnb [SEQ * N_EMBD];
__device__ __nv_bfloat16 g_projb[SEQ * PROJ];
__device__ float         g_aux [SEQ * AUX_W];
__device__ __nv_bfloat16 g_hb  [SEQ * D_INNER];
__device__ float         g_dt  [N_HEADS * SEQ];
__device__ float         g_la  [N_HEADS * SEQ];
__device__ __nv_bfloat16 g_Gb  [SEQ * SEQ];
__device__ float         g_part[4 * SEQ * N_EMBD];       // GEMM2 split-K partials
__device__ __nv_bfloat16 g_ypart[2 * SEQ * D_INNER];     // attn partials, bf16
__device__ __nv_bfloat16 g_yb  [SEQ * D_INNER];
__device__ __nv_bfloat16 g_w1b [N_EMBD * PROJ];
__device__ __nv_bfloat16 g_w2b [D_INNER * N_EMBD];

#define W1_BLKS   4256
#define W2_BLKS   2048
#define CONV_BLKS 4096
#define DT_BLKS   4
#define CBT_BLKS  64
#define K1_CTAS   272
#define K3_CTAS   256

// ---------------- software grid barrier ----------------
__device__ unsigned g_cnt = 0;
__device__ unsigned g_gen = 0;

__device__ __forceinline__ void gsync(unsigned n) {
    __syncthreads();
    if (threadIdx.x == 0) {
        unsigned gen = *((volatile unsigned*)&g_gen);
        __threadfence();
        if (atomicInc(&g_cnt, n - 1) == n - 1) {
            atomicAdd(&g_gen, 1);
        } else {
            while (*((volatile unsigned*)&g_gen) == gen) {}
        }
        __threadfence();
    }
    __syncthreads();
}

__device__ __forceinline__ float siluf(float v) {
    return v / (1.0f + __expf(-v));
}
__device__ __forceinline__ uint32_t smem_u32(const void* p) {
    uint32_t a;
    asm("{ .reg .u64 tmp; cvta.to.shared.u64 tmp, %1; cvt.u32.u64 %0, tmp; }"
        : "=r"(a) : "l"(p));
    return a;
}
__device__ __forceinline__ void cp_async16(uint32_t dst, const void* src) {
    asm volatile("cp.async.cg.shared.global [%0], [%1], 16;\n"
                 :: "r"(dst), "l"(src) : "memory");
}
__device__ __forceinline__ void cp_commit() {
    asm volatile("cp.async.commit_group;\n" ::: "memory");
}
template<int NN> __device__ __forceinline__ void cp_wait() {
    asm volatile("cp.async.wait_group %0;\n" :: "n"(NN) : "memory");
}

// ================= bf16 WMMA GEMM tile (device fn) =================
// B row-major [K][N]. BF16OUT=0: fp32 C (+z slice). BF16OUT=1: bf16 Cb +
// fp32 aux for cols >= AUX_COL0.
template<int BF16OUT>
__device__ void gemm_tile(__nv_bfloat16* dsm,
                          const __nv_bfloat16* __restrict__ A,
                          const __nv_bfloat16* __restrict__ B,
                          float* __restrict__ C,
                          __nv_bfloat16* __restrict__ Cb,
                          float* __restrict__ aux,
                          int M, int N, int Ktot, int Kslice,
                          int bm, int bn, int kz)
{
    constexpr int BM = 64, BN = 128, WARPS_N = 4;
    constexpr int THREADS = 256;
    constexpr int BK  = 64;
    constexpr int LDA = BK + 8;
    constexpr int LDB = BN + 8;
    constexpr int WM  = 32, WN = 32;
    constexpr int MF  = 2, NF = 2;
    constexpr int LDW = WN + 4;          // 36 floats = 144B rows
    constexpr int A_CH = BK / 8;
    constexpr int B_CH = BN / 8;
    constexpr int A_IT = (BM * A_CH) / THREADS;
    constexpr int B_IT = (BK * B_CH) / THREADS;

    __nv_bfloat16* As = dsm;                    // [2][BM][LDA]
    __nv_bfloat16* Bs = dsm + 2 * BM * LDA;     // [2][BK][LDB]

    const int tid = threadIdx.x;
    const int wid = tid >> 5;
    const int lane = tid & 31;
    const int wy  = wid / WARPS_N;
    const int wx  = wid % WARPS_N;
    const int kbase = kz * Kslice;
    float* Cz = C + (size_t)kz * M * N;

    wmma::fragment<wmma::accumulator, 16, 16, 16, float> acc[MF][NF];
    #pragma unroll
    for (int i = 0; i < MF; i++)
        #pragma unroll
        for (int j = 0; j < NF; j++)
            wmma::fill_fragment(acc[i][j], 0.0f);

    auto load_stage = [&](int i, int s) {
        int k0 = kbase + i * BK;
        uint32_t zero = 0;
        #pragma unroll
        for (int l = 0; l < A_IT; l++) {
            int idx = tid + l * THREADS;
            int row = idx / A_CH;
            int c8  = (idx % A_CH) * 8;
            cp_async16(smem_u32(As + (size_t)s * BM * LDA + row * LDA + c8),
                       A + (size_t)(bm + row) * Ktot + k0 + c8);
        }
        #pragma unroll
        for (int l = 0; l < B_IT; l++) {
            int idx = tid + l * THREADS;
            int row = idx / B_CH;
            int c8  = (idx % B_CH) * 8;
            uint32_t dst = smem_u32(Bs + (size_t)s * BK * LDB + row * LDB + c8);
            if (bn + c8 < N)
                cp_async16(dst, B + (size_t)(k0 + row) * N + bn + c8);
            else
                asm volatile("st.shared.v4.b32 [%0], {%1,%1,%1,%1};"
                             :: "r"(dst), "r"(zero) : "memory");
        }
        cp_commit();
    };

    const int NC = Kslice / BK;
    load_stage(0, 0);

    for (int i = 0; i < NC; i++) {
        int s = i & 1;
        if (i + 1 < NC) {
            load_stage(i + 1, s ^ 1);
            cp_wait<1>();
        } else {
            cp_wait<0>();
        }
        __syncthreads();

        const __nv_bfloat16* Asb = As + (size_t)s * BM * LDA;
        const __nv_bfloat16* Bsb = Bs + (size_t)s * BK * LDB;
        #pragma unroll
        for (int kk = 0; kk < BK; kk += 16) {
            wmma::fragment<wmma::matrix_a, 16, 16, 16,
                           __nv_bfloat16, wmma::row_major> af[MF];
            wmma::fragment<wmma::matrix_b, 16, 16, 16,
                           __nv_bfloat16, wmma::row_major> bf[NF];
            #pragma unroll
            for (int m = 0; m < MF; m++)
                wmma::load_matrix_sync(af[m],
                    Asb + (wy * WM + m * 16) * LDA + kk, LDA);
            #pragma unroll
            for (int n = 0; n < NF; n++)
                wmma::load_matrix_sync(bf[n],
                    Bsb + kk * LDB + wx * WN + n * 16, LDB);
            #pragma unroll
            for (int m = 0; m < MF; m++)
                #pragma unroll
                for (int n = 0; n < NF; n++)
                    wmma::mma_sync(acc[m][n], af[m], bf[n], acc[m][n]);
        }
        __syncthreads();
    }

    if (BF16OUT == 0) {
        #pragma unroll
        for (int m = 0; m < MF; m++) {
            int row0 = bm + wy * WM + m * 16;
            #pragma unroll
            for (int n = 0; n < NF; n++) {
                int col0 = bn + wx * WN + n * 16;
                if (col0 < N)
                    wmma::store_matrix_sync(&Cz[(size_t)row0 * N + col0],
                                            acc[m][n], N, wmma::mem_row_major);
            }
        }
    } else {
        float* ws = reinterpret_cast<float*>(dsm) + wid * (WM * LDW);
        #pragma unroll
        for (int m = 0; m < MF; m++)
            #pragma unroll
            for (int n = 0; n < NF; n++)
                wmma::store_matrix_sync(ws + (m * 16) * LDW + n * 16,
                                        acc[m][n], LDW, wmma::mem_row_major);
        __syncwarp();
        int r0g = bm + wy * WM;
        int c0g = bn + wx * WN;
        #pragma unroll
        for (int e = 0; e < WM * WN / 2 / 32; e++) {
            int idx = lane + e * 32;
            int row = idx / (WN / 2);
            int c2  = (idx % (WN / 2)) * 2;
            int gc  = c0g + c2;
            if (gc < N) {
                float v0 = ws[row * LDW + c2];
                float v1 = ws[row * LDW + c2 + 1];
                __nv_bfloat162 pk = __floats2bfloat162_rn(v0, v1);
                *reinterpret_cast<__nv_bfloat162*>(
                    &Cb[(size_t)(r0g + row) * N + gc]) = pk;
                if (gc >= AUX_COL0) {
                    aux[(size_t)(r0g + row) * AUX_W + gc - AUX_COL0]     = v0;
                    aux[(size_t)(r0g + row) * AUX_W + gc - AUX_COL0 + 1] = v1;
                }
            }
        }
        __syncthreads();   // ws (dsm) idle before next phase
    }
}

// ================= K1: prologue | GEMM1 | mid (grid barrier fused) ========
__global__ void __launch_bounds__(256, 2)
mega1_kernel(const float* __restrict__ w_in,
             const float* __restrict__ w_out,
             const float* __restrict__ x,
             const float* __restrict__ nscale,
             const float* __restrict__ conv_w,
             const float* __restrict__ conv_b,
             const float* __restrict__ dt_bias,
             const float* __restrict__ A_log,
             __nv_bfloat16* __restrict__ w1b,
             __nv_bfloat16* __restrict__ w2b,
             __nv_bfloat16* __restrict__ xnb,
             __nv_bfloat16* __restrict__ projb,
             float* __restrict__ aux,
             __nv_bfloat16* __restrict__ hb,
             float* __restrict__ dtb,
             float* __restrict__ lab,
             __nv_bfloat16* __restrict__ Gm)
{
    extern __shared__ __nv_bfloat16 dsm[];
    const int tid = threadIdx.x;

    // ---- phase A: weight casts + rmsnorm (grid-stride) ----
    for (int vb = blockIdx.x; vb < W1_BLKS + W2_BLKS + SEQ; vb += K1_CTAS) {
        if (vb < W1_BLKS + W2_BLKS) {
            const float* in;
            __nv_bfloat16* out;
            int i;
            if (vb < W1_BLKS) { in = w_in;  out = w1b; i = vb * 256 + tid; }
            else              { in = w_out; out = w2b; i = (vb - W1_BLKS) * 256 + tid; }
            float4 v = reinterpret_cast<const float4*>(in)[i];
            __nv_bfloat162 a2 = __floats2bfloat162_rn(v.x, v.y);
            __nv_bfloat162 b2 = __floats2bfloat162_rn(v.z, v.w);
            uint2 pk;
            pk.x = *reinterpret_cast<uint32_t*>(&a2);
            pk.y = *reinterpret_cast<uint32_t*>(&b2);
            reinterpret_cast<uint2*>(out)[i] = pk;
        } else {
            int row = vb - (W1_BLKS + W2_BLKS);
            float4 v = reinterpret_cast<const float4*>(x + row * N_EMBD)[tid];
            float ss = v.x * v.x + v.y * v.y + v.z * v.z + v.w * v.w;
            #pragma unroll
            for (int o = 16; o; o >>= 1) ss += __shfl_xor_sync(0xffffffffu, ss, o);
            __shared__ float wsum[8];
            int lane = tid & 31, wd = tid >> 5;
            if (lane == 0) wsum[wd] = ss;
            __syncthreads();
            __shared__ float s_inv;
            if (tid == 0) {
                float tot = 0.f;
                #pragma unroll
                for (int i = 0; i < 8; i++) tot += wsum[i];
                s_inv = rsqrtf(tot / (float)N_EMBD + 1e-6f);
            }
            __syncthreads();
            float inv = s_inv;
            const float4 sc = reinterpret_cast<const float4*>(nscale)[tid];
            __nv_bfloat162 o01 = __floats2bfloat162_rn(v.x * inv * sc.x, v.y * inv * sc.y);
            __nv_bfloat162 o23 = __floats2bfloat162_rn(v.z * inv * sc.z, v.w * inv * sc.w);
            uint2 pk;
            pk.x = *reinterpret_cast<uint32_t*>(&o01);
            pk.y = *reinterpret_cast<uint32_t*>(&o23);
            *reinterpret_cast<uint2*>(xnb + row * N_EMBD + tid * 4) = pk;
            __syncthreads();   // protect s_inv/wsum across grid-stride iters
        }
    }
    gsync(K1_CTAS);

    // ---- phase B: GEMM1 tile ----
    {
        int bx = blockIdx.x % 34;
        int by = blockIdx.x / 34;
        gemm_tile<1>(dsm, xnb, w1b, nullptr, projb, aux,
                     SEQ, PROJ, N_EMBD, N_EMBD, by * 64, bx * 128, 0);
    }
    gsync(K1_CTAS);

    // ---- phase C: conv | dt scan | cbt (grid-stride) ----
    for (int vb = blockIdx.x; vb < CONV_BLKS + DT_BLKS + CBT_BLKS; vb += K1_CTAS) {
        if (vb < CONV_BLKS) {
            int i = vb * 256 + tid;
            int t = i >> 11;
            int c = i & (D_INNER - 1);
            float acc = conv_b[c];
            #pragma unroll
            for (int k = 0; k < D_CONV; k++) {
                int s = t + k - (D_CONV - 1);
                if (s >= 0)
                    acc += conv_w[k * D_INNER + c] *
                           __bfloat162float(projb[(size_t)s * PROJ + COL_SSM + c]);
            }
            hb[i] = __float2bfloat16(siluf(acc));
        } else if (vb < CONV_BLKS + DT_BLKS) {
            int head = (vb - CONV_BLKS) * 8 + (tid >> 5);
            int lane = tid & 31;
            float bv = dt_bias[head];
            float A = -expf(A_log[head]);
            float vals[16];
            float run = 0.f;
            #pragma unroll
            for (int i = 0; i < 16; i++) {
                int t = lane * 16 + i;
                float z = aux[(size_t)t * AUX_W + head] + bv;
                float d = (z > 20.f) ? z : log1pf(__expf(z));
                dtb[head * SEQ + t] = d;
                run += A * d;
                vals[i] = run;
            }
            float tot = run;
            #pragma unroll
            for (int off = 1; off < 32; off <<= 1) {
                float nb = __shfl_up_sync(0xffffffffu, tot, off);
                if (lane >= off) tot += nb;
            }
            float excl = tot - run;
            #pragma unroll
            for (int i = 0; i < 16; i++)
                lab[head * SEQ + lane * 16 + i] = vals[i] + excl;
        } else {
            // cbt tile in dynamic smem: Csh[64][65], Bsh[64][65]
            float* Csh = reinterpret_cast<float*>(dsm);
            float* Bsh = Csh + 64 * 65;
            int id = vb - (CONV_BLKS + DT_BLKS);
            int s0 = (id & 7) * 64;
            int t0 = (id >> 3) * 64;
            __syncthreads();   // smem reuse guard across grid-stride iters
            #pragma unroll
            for (int l = 0; l < 16; l++) {
                int idx = tid + l * 256;
                int r = idx >> 6;
                int n = idx & 63;
                Csh[n * 65 + r] = aux[(size_t)(t0 + r) * AUX_W + 96 + n];
                Bsh[n * 65 + r] = aux[(size_t)(s0 + r) * AUX_W + 32 + n];
            }
            __syncthreads();
            int ty = tid / 16, tx = tid % 16;
            int r0 = ty * 4, c0 = tx * 4;
            float acc[4][4];
            #pragma unroll
            for (int i = 0; i < 4; i++)
                #pragma unroll
                for (int j = 0; j < 4; j++) acc[i][j] = 0.f;
            #pragma unroll
            for (int k = 0; k < D_STATE; k++) {
                float ra[4], rb[4];
                #pragma unroll
                for (int i = 0; i < 4; i++) ra[i] = Csh[k * 65 + r0 + i];
                #pragma unroll
                for (int j = 0; j < 4; j++) rb[j] = Bsh[k * 65 + c0 + j];
                #pragma unroll
                for (int i = 0; i < 4; i++)
                    #pragma unroll
                    for (int j = 0; j < 4; j++) acc[i][j] += ra[i] * rb[j];
            }
            #pragma unroll
            for (int i = 0; i < 4; i++)
                #pragma unroll
                for (int j = 0; j < 4; j++) {
                    int tt = t0 + r0 + i, ssd = s0 + c0 + j;
                    Gm[(size_t)tt * SEQ + ssd] =
                        (ssd <= tt) ? __float2bfloat16(acc[i][j])
                                    : __float2bfloat16(0.f);
                }
        }
    }
}

// ---------------- SSM attention: split-s double-tile pipelined WMMA ------
#define TILE_E (64 * 72)
#define ATTN_SMEM (2 * 4 * TILE_E * 2)   // 73728

__global__ void __launch_bounds__(256)
attn_kernel(const __nv_bfloat16* __restrict__ Gm,
            const __nv_bfloat16* __restrict__ hb,
            const float* __restrict__ la,
            const float* __restrict__ dt,
            __nv_bfloat16* __restrict__ ypart) {
    extern __shared__ char dsm8[];
    __nv_bfloat16* Gs = (__nv_bfloat16*)dsm8;
    __nv_bfloat16* Xs = (__nv_bfloat16*)dsm8 + 4 * TILE_E;
    float* Ys = (float*)dsm8;

    __shared__ __nv_bfloat162 es2[256];
    __shared__ float          etf[64];

    const int bidx = blockIdx.x;
    const int ti   = (bidx < 4) ? bidx : 11 - bidx;
    const int head = blockIdx.y;
    const int zz   = blockIdx.z;
    const int t0   = ti * 64;
    const int tid  = threadIdx.x;
    const int wid  = tid >> 5;
    const int wy   = wid >> 1;
    const int wx   = wid & 1;

    const float* laH = la + head * SEQ;
    const float* dtH = dt + head * SEQ;
    const int NT = ti + 1;
    const int ND = (NT + 1) >> 1;
    const int smax = t0 + 63;

    int dlist[2];
    int nd = 0;
    for (int d = zz; d < ND; d += 2) dlist[nd++] = d;

    {
        float la_r = laH[t0];
        for (int i = tid; i < ND * 64; i += 256) {
            int s = 2 * i;
            float a0 = (s     <= smax) ? __expf(la_r - laH[s])     * dtH[s]     : 0.f;
            float a1 = (s + 1 <= smax) ? __expf(la_r - laH[s + 1]) * dtH[s + 1] : 0.f;
            es2[i] = __floats2bfloat162_rn(a0, a1);
        }
        if (tid < 64)
            etf[tid] = __expf(laH[t0 + tid] - la_r);
    }

    auto issue = [&](int d, int sb) {
        int s0 = d * 128;
        #pragma unroll
        for (int l = 0; l < 4; l++) {
            int idx = tid + l * 256;
            int slot = sb + (idx >> 9);
            int r    = (idx >> 3) & 63;
            int c16  = (idx & 7) * 16;
            int scol = s0 + ((idx >> 9) << 6);
            cp_async16(smem_u32(Gs + slot * TILE_E + r * 72) + c16,
                       (const char*)(Gm + (size_t)(t0 + r) * SEQ + scol) + c16);
            cp_async16(smem_u32(Xs + slot * TILE_E + r * 72) + c16,
                       (const char*)(hb + (size_t)(scol + r) * D_INNER
                                        + head * HEAD_DIM) + c16);
        }
        cp_commit();
    };

    wmma::fragment<wmma::accumulator, 16, 16, 16, float> acc[2];
    wmma::fill_fragment(acc[0], 0.0f);
    wmma::fill_fragment(acc[1], 0.0f);

    if (nd > 0) issue(dlist[0], 0);
    if (nd > 1) issue(dlist[1], 2);

    for (int i = 0; i < nd; i++) {
        int d  = dlist[i];
        int sb = 2 * i;
        if (i + 1 < nd) cp_wait<1>(); else cp_wait<0>();
        __syncthreads();

        #pragma unroll
        for (int hh = 0; hh < 2; hh++) {
            __nv_bfloat16* Gb = Gs + (sb + hh) * TILE_E;
            const int esBase = d * 64 + hh * 32;
            #pragma unroll
            for (int l = 0; l < 4; l++) {
                int u   = tid + l * 256;
                int tl  = u >> 4;
                int sl4 = (u & 15) * 4;
                uint2* p = reinterpret_cast<uint2*>(Gb + tl * 72 + sl4);
                uint2 v = *p;
                __nv_bfloat162 g0 = *reinterpret_cast<__nv_bfloat162*>(&v.x);
                __nv_bfloat162 g1 = *reinterpret_cast<__nv_bfloat162*>(&v.y);
                g0 = __hmul2(g0, es2[esBase + (sl4 >> 1)]);
                g1 = __hmul2(g1, es2[esBase + (sl4 >> 1) + 1]);
                v.x = *reinterpret_cast<uint32_t*>(&g0);
                v.y = *reinterpret_cast<uint32_t*>(&g1);
                *p = v;
            }
        }
        __syncthreads();

        #pragma unroll
        for (int hh = 0; hh < 2; hh++) {
            __nv_bfloat16* Gb = Gs + (sb + hh) * TILE_E;
            __nv_bfloat16* Xb = Xs + (sb + hh) * TILE_E;
            #pragma unroll
            for (int ks = 0; ks < 4; ks++) {
                wmma::fragment<wmma::matrix_a, 16, 16, 16,
                               __nv_bfloat16, wmma::row_major> af;
                wmma::load_matrix_sync(af, Gb + (wy * 16) * 72 + ks * 16, 72);
                #pragma unroll
                for (int n = 0; n < 2; n++) {
                    wmma::fragment<wmma::matrix_b, 16, 16, 16,
                                   __nv_bfloat16, wmma::row_major> bf;
                    wmma::load_matrix_sync(bf,
                        Xb + (ks * 16) * 72 + wx * 32 + n * 16, 72);
                    wmma::mma_sync(acc[n], af, bf, acc[n]);
                }
            }
        }
    }

    __syncthreads();
    #pragma unroll
    for (int n = 0; n < 2; n++)
        wmma::store_matrix_sync(Ys + (wy * 16) * 68 + wx * 32 + n * 16, acc[n],
                                68, wmma::mem_row_major);
    __syncthreads();
    __nv_bfloat16* yz = ypart + (size_t)zz * SEQ * D_INNER;
    #pragma unroll
    for (int l = 0; l < 16; l++) {
        int idx = tid + l * 256;
        int row = idx >> 6, col = idx & 63;
        yz[(size_t)(t0 + row) * D_INNER + head * HEAD_DIM + col] =
            __float2bfloat16(Ys[row * 68 + col] * etf[row]);
    }
}

// ================= K3: gate | GEMM2 | combine (grid barrier fused) ========
__global__ void __launch_bounds__(256, 2)
mega3_kernel(const __nv_bfloat16* __restrict__ ypart,
             const __nv_bfloat16* __restrict__ projb,
             const __nv_bfloat16* __restrict__ w2b,
             const float* __restrict__ x,
             __nv_bfloat16* __restrict__ yb,
             float* __restrict__ part,
             float* __restrict__ out)
{
    extern __shared__ __nv_bfloat16 dsm[];
    const int tid = threadIdx.x;

    // ---- phase A: gate yb = bf16((p0+p1)*silu(gate)) ----
    for (int vb = blockIdx.x; vb < (SEQ * D_INNER / 4) / 256; vb += K3_CTAS) {
        int i = vb * 256 + tid;      // index over 4-elem groups
        int e = i * 4;
        int t = e >> 11;
        int c = e & (D_INNER - 1);
        uint2 u0 = reinterpret_cast<const uint2*>(ypart)[i];
        uint2 u1 = reinterpret_cast<const uint2*>(ypart + SEQ * D_INNER)[i];
        uint2 gp = *reinterpret_cast<const uint2*>(
            &projb[(size_t)t * PROJ + COL_GATE + c]);
        __nv_bfloat162 p0a = *reinterpret_cast<__nv_bfloat162*>(&u0.x);
        __nv_bfloat162 p0b = *reinterpret_cast<__nv_bfloat162*>(&u0.y);
        __nv_bfloat162 p1a = *reinterpret_cast<__nv_bfloat162*>(&u1.x);
        __nv_bfloat162 p1b = *reinterpret_cast<__nv_bfloat162*>(&u1.y);
        __nv_bfloat162 ga = *reinterpret_cast<__nv_bfloat162*>(&gp.x);
        __nv_bfloat162 gb = *reinterpret_cast<__nv_bfloat162*>(&gp.y);
        float y0 = (__bfloat162float(p0a.x) + __bfloat162float(p1a.x)) *
                   siluf(__bfloat162float(ga.x));
        float y1 = (__bfloat162float(p0a.y) + __bfloat162float(p1a.y)) *
                   siluf(__bfloat162float(ga.y));
        float y2 = (__bfloat162float(p0b.x) + __bfloat162float(p1b.x)) *
                   siluf(__bfloat162float(gb.x));
        float y3 = (__bfloat162float(p0b.y) + __bfloat162float(p1b.y)) *
                   siluf(__bfloat162float(gb.y));
        __nv_bfloat162 o0 = __floats2bfloat162_rn(y0, y1);
        __nv_bfloat162 o1 = __floats2bfloat162_rn(y2, y3);
        uint2 pk;
        pk.x = *reinterpret_cast<uint32_t*>(&o0);
        pk.y = *reinterpret_cast<uint32_t*>(&o1);
        *reinterpret_cast<uint2*>(&yb[e]) = pk;
    }
    gsync(K3_CTAS);

    // ---- phase B: GEMM2 split-K tile ----
    {
        int bx = blockIdx.x % 8;          // N tile
        int by = (blockIdx.x / 8) % 8;    // M tile
        int bz = blockIdx.x / 64;         // K slice
        gemm_tile<0>(dsm, yb, w2b, part, nullptr, nullptr,
                     SEQ, N_EMBD, D_INNER, D_INNER / 4,
                     by * 64, bx * 128, bz);
    }
    gsync(K3_CTAS);

    // ---- phase C: combine out = x + sum part ----
    for (int vb = blockIdx.x; vb < (SEQ * N_EMBD / 4) / 256; vb += K3_CTAS) {
        int i = vb * 256 + tid;
        float4 a = reinterpret_cast<const float4*>(x)[i];
        #pragma unroll
        for (int z = 0; z < 4; z++) {
            float4 p = reinterpret_cast<const float4*>(
                part + (size_t)z * SEQ * N_EMBD)[i];
            a.x += p.x;  a.y += p.y;  a.z += p.z;  a.w += p.w;
        }
        reinterpret_cast<float4*>(out)[i] = a;
    }
}

// ---------------- host launch ----------------
#define GEMM_SMEM (2 * 64 * 72 * 2 + 2 * 64 * 136 * 2)   // 53248

extern "C" void kernel_launch(void* const* d_in, const int* in_sizes, int n_in,
                              void* d_out, int out_size) {
    const float* x        = (const float*)d_in[0];
    const float* nscale   = (const float*)d_in[1];
    const float* w_in     = (const float*)d_in[2];
    const float* conv_w   = (const float*)d_in[3];
    const float* conv_b   = (const float*)d_in[4];
    const float* A_log    = (const float*)d_in[5];
    const float* dt_bias  = (const float*)d_in[6];
    const float* w_out    = (const float*)d_in[7];
    float* out = (float*)d_out;

    void *p_xnb, *p_projb, *p_aux, *p_hb, *p_dt, *p_la, *p_G, *p_part,
         *p_yp, *p_yb, *p_w1, *p_w2;
    cudaGetSymbolAddress(&p_xnb,   g_xnb);
    cudaGetSymbolAddress(&p_projb, g_projb);
    cudaGetSymbolAddress(&p_aux,   g_aux);
    cudaGetSymbolAddress(&p_hb,    g_hb);
    cudaGetSymbolAddress(&p_dt,    g_dt);
    cudaGetSymbolAddress(&p_la,    g_la);
    cudaGetSymbolAddress(&p_G,     g_Gb);
    cudaGetSymbolAddress(&p_part,  g_part);
    cudaGetSymbolAddress(&p_yp,    g_ypart);
    cudaGetSymbolAddress(&p_yb,    g_yb);
    cudaGetSymbolAddress(&p_w1,    g_w1b);
    cudaGetSymbolAddress(&p_w2,    g_w2b);
    __nv_bfloat16* xnb   = (__nv_bfloat16*)p_xnb;
    __nv_bfloat16* projb = (__nv_bfloat16*)p_projb;
    float*         aux   = (float*)p_aux;
    __nv_bfloat16* hb    = (__nv_bfloat16*)p_hb;
    float*         dt    = (float*)p_dt;
    float*         la    = (float*)p_la;
    __nv_bfloat16* Gmb   = (__nv_bfloat16*)p_G;
    float*         part  = (float*)p_part;
    __nv_bfloat16* ypart = (__nv_bfloat16*)p_yp;
    __nv_bfloat16* ybuf  = (__nv_bfloat16*)p_yb;
    __nv_bfloat16* w1b   = (__nv_bfloat16*)p_w1;
    __nv_bfloat16* w2b   = (__nv_bfloat16*)p_w2;

    cudaFuncSetAttribute(mega1_kernel,
        cudaFuncAttributeMaxDynamicSharedMemorySize, GEMM_SMEM);
    cudaFuncSetAttribute(mega3_kernel,
        cudaFuncAttributeMaxDynamicSharedMemorySize, GEMM_SMEM);
    cudaFuncSetAttribute(attn_kernel,
        cudaFuncAttributeMaxDynamicSharedMemorySize, ATTN_SMEM);

    // K1: prologue -> GEMM1 -> mid, one launch (grid barrier)
    mega1_kernel<<<K1_CTAS, 256, GEMM_SMEM>>>(
        w_in, w_out, x, nscale, conv_w, conv_b, dt_bias, A_log,
        w1b, w2b, xnb, projb, aux, hb, dt, la, Gmb);

    // K2: attn split-s (512 CTAs, bf16 partials)
    attn_kernel<<<dim3(SEQ / 64, N_HEADS, 2), 256, ATTN_SMEM>>>(
        Gmb, hb, la, dt, ypart);

    // K3: gate -> GEMM2 -> combine, one launch (grid barrier)
    mega3_kernel<<<K3_CTAS, 256, GEMM_SMEM>>>(
        ypart, projb, w2b, x, ybuf, part, out);
}

// round 15
// speedup vs baseline: 1.1183x; 1.1183x over previous
#include <cuda_runtime.h>
#include <cuda_bf16.h>
#include <mma.h>
#include <cstdint>
#include <math.h>

using namespace nvcuda;

// ---------------- problem constants ----------------
#define N_EMBD   1024
#define D_INNER  2048
#define D_STATE  64
#define N_HEADS  32
#define HEAD_DIM 64
#define D_CONV   4
#define SEQ      512
#define PROJ     4256          // 2*D_INNER + N_HEADS + 2*N_GROUPS*D_STATE
#define COL_GATE 0
#define COL_SSM  2048
#define AUX_COL0 4096          // dt(32) | B(64) | C(64) live in fp32 aux
#define AUX_W    160

// ---------------- scratch (no allocation allowed) ----------------
__device__ __nv_bfloat16 g_xnb [SEQ * N_EMBD];
__device__ __nv_bfloat16 g_projb[SEQ * PROJ];
__device__ float         g_aux [SEQ * AUX_W];
__device__ __nv_bfloat16 g_hb  [SEQ * D_INNER];
__device__ float         g_dt  [N_HEADS * SEQ];
__device__ float         g_la  [N_HEADS * SEQ];
__device__ __nv_bfloat16 g_Gb  [SEQ * SEQ];
__device__ float         g_part[4 * SEQ * N_EMBD];   // GEMM2 split-K partials
__device__ __nv_bfloat16 g_ypart[2 * SEQ * D_INNER]; // attn partials (bf16)
__device__ __nv_bfloat16 g_yb  [SEQ * D_INNER];
__device__ __nv_bfloat16 g_w1b [N_EMBD * PROJ];
__device__ __nv_bfloat16 g_w2b [D_INNER * N_EMBD];

#define W1_BLKS   4256
#define W2_BLKS   2048
#define CONV_BLKS 4096
#define DT_BLKS   4
#define CBT_BLKS  64

__device__ __forceinline__ float siluf(float v) {
    return v / (1.0f + __expf(-v));
}
__device__ __forceinline__ uint32_t smem_u32(const void* p) {
    uint32_t a;
    asm("{ .reg .u64 tmp; cvta.to.shared.u64 tmp, %1; cvt.u32.u64 %0, tmp; }"
        : "=r"(a) : "l"(p));
    return a;
}
__device__ __forceinline__ void cp_async16(uint32_t dst, const void* src) {
    asm volatile("cp.async.cg.shared.global [%0], [%1], 16;\n"
                 :: "r"(dst), "l"(src) : "memory");
}
__device__ __forceinline__ void cp_commit() {
    asm volatile("cp.async.commit_group;\n" ::: "memory");
}
template<int NN> __device__ __forceinline__ void cp_wait() {
    asm volatile("cp.async.wait_group %0;\n" :: "n"(NN) : "memory");
}

// ================= bf16 WMMA GEMM (B row-major [K][N]) =================
// BF16OUT=0: fp32 C (split-K partials).  BF16OUT=1: bf16 Cb + fp32 aux for
// global cols >= AUX_COL0 (GEMM1 path).
template<int BM, int BN, int WARPS_M, int WARPS_N, int BF16OUT>
__global__ void __launch_bounds__(WARPS_M * WARPS_N * 32, 2)
bf16_gemm_kernel(const __nv_bfloat16* __restrict__ A,
                 const __nv_bfloat16* __restrict__ B,
                 float* __restrict__ C,
                 __nv_bfloat16* __restrict__ Cb,
                 float* __restrict__ aux,
                 int M, int N, int Ktot, int Kslice)
{
    constexpr int THREADS = WARPS_M * WARPS_N * 32;
    constexpr int BK  = 64;
    constexpr int LDA = BK + 8;          // halves
    constexpr int LDB = BN + 8;
    constexpr int WM  = BM / WARPS_M;
    constexpr int WN  = BN / WARPS_N;
    constexpr int MF  = WM / 16;
    constexpr int NF  = WN / 16;
    constexpr int LDW = WN + 4;          // 36 floats = 144B rows (16B aligned)
    constexpr int A_CH = BK / 8;
    constexpr int B_CH = BN / 8;
    constexpr int A_IT = (BM * A_CH) / THREADS;
    constexpr int B_IT = (BK * B_CH) / THREADS;

    extern __shared__ __nv_bfloat16 dsm[];
    __nv_bfloat16* As = dsm;                    // [2][BM][LDA]
    __nv_bfloat16* Bs = dsm + 2 * BM * LDA;     // [2][BK][LDB]

    const int tid = threadIdx.x;
    const int wid = tid >> 5;
    const int lane = tid & 31;
    const int wy  = wid / WARPS_N;
    const int wx  = wid % WARPS_N;
    const int bm  = blockIdx.y * BM;
    const int bn  = blockIdx.x * BN;
    const int kbase = blockIdx.z * Kslice;
    float* Cz = C + (size_t)blockIdx.z * M * N;

    wmma::fragment<wmma::accumulator, 16, 16, 16, float> acc[MF][NF];
    #pragma unroll
    for (int i = 0; i < MF; i++)
        #pragma unroll
        for (int j = 0; j < NF; j++)
            wmma::fill_fragment(acc[i][j], 0.0f);

    auto load_stage = [&](int i, int s) {
        int k0 = kbase + i * BK;
        uint32_t zero = 0;
        #pragma unroll
        for (int l = 0; l < A_IT; l++) {
            int idx = tid + l * THREADS;
            int row = idx / A_CH;
            int c8  = (idx % A_CH) * 8;
            cp_async16(smem_u32(As + (size_t)s * BM * LDA + row * LDA + c8),
                       A + (size_t)(bm + row) * Ktot + k0 + c8);
        }
        #pragma unroll
        for (int l = 0; l < B_IT; l++) {
            int idx = tid + l * THREADS;
            int row = idx / B_CH;
            int c8  = (idx % B_CH) * 8;
            uint32_t dst = smem_u32(Bs + (size_t)s * BK * LDB + row * LDB + c8);
            if (bn + c8 < N)
                cp_async16(dst, B + (size_t)(k0 + row) * N + bn + c8);
            else
                asm volatile("st.shared.v4.b32 [%0], {%1,%1,%1,%1};"
                             :: "r"(dst), "r"(zero) : "memory");
        }
        cp_commit();
    };

    const int NC = Kslice / BK;
    load_stage(0, 0);

    for (int i = 0; i < NC; i++) {
        int s = i & 1;
        if (i + 1 < NC) {
            load_stage(i + 1, s ^ 1);
            cp_wait<1>();
        } else {
            cp_wait<0>();
        }
        __syncthreads();

        const __nv_bfloat16* Asb = As + (size_t)s * BM * LDA;
        const __nv_bfloat16* Bsb = Bs + (size_t)s * BK * LDB;
        #pragma unroll
        for (int kk = 0; kk < BK; kk += 16) {
            wmma::fragment<wmma::matrix_a, 16, 16, 16,
                           __nv_bfloat16, wmma::row_major> af[MF];
            wmma::fragment<wmma::matrix_b, 16, 16, 16,
                           __nv_bfloat16, wmma::row_major> bf[NF];
            #pragma unroll
            for (int m = 0; m < MF; m++)
                wmma::load_matrix_sync(af[m],
                    Asb + (wy * WM + m * 16) * LDA + kk, LDA);
            #pragma unroll
            for (int n = 0; n < NF; n++)
                wmma::load_matrix_sync(bf[n],
                    Bsb + kk * LDB + wx * WN + n * 16, LDB);
            #pragma unroll
            for (int m = 0; m < MF; m++)
                #pragma unroll
                for (int n = 0; n < NF; n++)
                    wmma::mma_sync(acc[m][n], af[m], bf[n], acc[m][n]);
        }
        __syncthreads();
    }

    if (BF16OUT == 0) {
        #pragma unroll
        for (int m = 0; m < MF; m++) {
            int row0 = bm + wy * WM + m * 16;
            #pragma unroll
            for (int n = 0; n < NF; n++) {
                int col0 = bn + wx * WN + n * 16;
                if (col0 < N)
                    wmma::store_matrix_sync(&Cz[(size_t)row0 * N + col0],
                                            acc[m][n], N, wmma::mem_row_major);
            }
        }
    } else {
        float* ws = reinterpret_cast<float*>(dsm) + wid * (WM * LDW);
        #pragma unroll
        for (int m = 0; m < MF; m++)
            #pragma unroll
            for (int n = 0; n < NF; n++)
                wmma::store_matrix_sync(ws + (m * 16) * LDW + n * 16,
                                        acc[m][n], LDW, wmma::mem_row_major);
        __syncwarp();
        int r0g = bm + wy * WM;
        int c0g = bn + wx * WN;
        #pragma unroll
        for (int e = 0; e < WM * WN / 2 / 32; e++) {
            int idx = lane + e * 32;
            int row = idx / (WN / 2);
            int c2  = (idx % (WN / 2)) * 2;
            int gc  = c0g + c2;
            if (gc < N) {
                float v0 = ws[row * LDW + c2];
                float v1 = ws[row * LDW + c2 + 1];
                __nv_bfloat162 pk = __floats2bfloat162_rn(v0, v1);
                *reinterpret_cast<__nv_bfloat162*>(
                    &Cb[(size_t)(r0g + row) * N + gc]) = pk;
                if (gc >= AUX_COL0) {
                    aux[(size_t)(r0g + row) * AUX_W + gc - AUX_COL0]     = v0;
                    aux[(size_t)(r0g + row) * AUX_W + gc - AUX_COL0 + 1] = v1;
                }
            }
        }
    }
}

// ================= fused prologue: weight casts + RMSNorm =================
__global__ void __launch_bounds__(256)
prologue_kernel(const float* __restrict__ w_in,
                const float* __restrict__ w_out,
                const float* __restrict__ x,
                const float* __restrict__ scale,
                __nv_bfloat16* __restrict__ w1b,
                __nv_bfloat16* __restrict__ w2b,
                __nv_bfloat16* __restrict__ xnb) {
    int b = blockIdx.x;
    int tid = threadIdx.x;
    if (b < W1_BLKS + W2_BLKS) {
        const float* in;
        __nv_bfloat16* out;
        int i;
        if (b < W1_BLKS) { in = w_in;  out = w1b; i = b * 256 + tid; }
        else             { in = w_out; out = w2b; i = (b - W1_BLKS) * 256 + tid; }
        float4 v = reinterpret_cast<const float4*>(in)[i];
        __nv_bfloat162 a2 = __floats2bfloat162_rn(v.x, v.y);
        __nv_bfloat162 b2 = __floats2bfloat162_rn(v.z, v.w);
        uint2 pk;
        pk.x = *reinterpret_cast<uint32_t*>(&a2);
        pk.y = *reinterpret_cast<uint32_t*>(&b2);
        reinterpret_cast<uint2*>(out)[i] = pk;
        return;
    }
    // ---- RMSNorm row ----
    int row = b - (W1_BLKS + W2_BLKS);
    const float4* xr = reinterpret_cast<const float4*>(x + row * N_EMBD);
    float4 v = xr[tid];
    float ss = v.x * v.x + v.y * v.y + v.z * v.z + v.w * v.w;
    #pragma unroll
    for (int o = 16; o; o >>= 1) ss += __shfl_xor_sync(0xffffffffu, ss, o);
    __shared__ float wsum[8];
    int lane = tid & 31, wid = tid >> 5;
    if (lane == 0) wsum[wid] = ss;
    __syncthreads();
    __shared__ float s_inv;
    if (tid == 0) {
        float tot = 0.f;
        #pragma unroll
        for (int i = 0; i < 8; i++) tot += wsum[i];
        s_inv = rsqrtf(tot / (float)N_EMBD + 1e-6f);
    }
    __syncthreads();
    float inv = s_inv;
    const float4 sc = reinterpret_cast<const float4*>(scale)[tid];
    __nv_bfloat162 o01 = __floats2bfloat162_rn(v.x * inv * sc.x, v.y * inv * sc.y);
    __nv_bfloat162 o23 = __floats2bfloat162_rn(v.z * inv * sc.z, v.w * inv * sc.w);
    uint2 pk;
    pk.x = *reinterpret_cast<uint32_t*>(&o01);
    pk.y = *reinterpret_cast<uint32_t*>(&o23);
    *reinterpret_cast<uint2*>(xnb + row * N_EMBD + tid * 4) = pk;
}

// ================= fused mid: conv+silu | dt+la scan | Gm =================
__global__ void __launch_bounds__(256)
mid_kernel(const __nv_bfloat16* __restrict__ projb,
           const float* __restrict__ aux,
           const float* __restrict__ w,
           const float* __restrict__ bias,
           const float* __restrict__ dt_bias,
           const float* __restrict__ A_log,
           __nv_bfloat16* __restrict__ h,
           float* __restrict__ dt_out,
           float* __restrict__ la_out,
           __nv_bfloat16* __restrict__ Gm) {
    int b = blockIdx.x;
    int tid = threadIdx.x;

    if (b < CONV_BLKS) {
        int i = b * 256 + tid;
        int t = i >> 11;
        int c = i & (D_INNER - 1);
        float acc = bias[c];
        #pragma unroll
        for (int k = 0; k < D_CONV; k++) {
            int s = t + k - (D_CONV - 1);
            if (s >= 0)
                acc += w[k * D_INNER + c] *
                       __bfloat162float(projb[(size_t)s * PROJ + COL_SSM + c]);
        }
        h[i] = __float2bfloat16(siluf(acc));
        return;
    }
    if (b < CONV_BLKS + DT_BLKS) {
        int head = (b - CONV_BLKS) * 8 + (tid >> 5);
        int lane = tid & 31;
        float bv = dt_bias[head];
        float A = -expf(A_log[head]);
        float vals[16];
        float run = 0.f;
        #pragma unroll
        for (int i = 0; i < 16; i++) {
            int t = lane * 16 + i;
            float z = aux[(size_t)t * AUX_W + head] + bv;
            float d = (z > 20.f) ? z : log1pf(__expf(z));
            dt_out[head * SEQ + t] = d;
            run += A * d;
            vals[i] = run;
        }
        float tot = run;
        #pragma unroll
        for (int off = 1; off < 32; off <<= 1) {
            float nb = __shfl_up_sync(0xffffffffu, tot, off);
            if (lane >= off) tot += nb;
        }
        float excl = tot - run;
        #pragma unroll
        for (int i = 0; i < 16; i++)
            la_out[head * SEQ + lane * 16 + i] = vals[i] + excl;
        return;
    }
    // ---- cbt tile: Gm[t][s] = (s<=t) ? bf16(C_t . B_s) : 0 ----
    {
        __shared__ float Csh[D_STATE][64 + 1];
        __shared__ float Bsh[D_STATE][64 + 1];
        int id = b - (CONV_BLKS + DT_BLKS);
        int s0 = (id & 7) * 64;
        int t0 = (id >> 3) * 64;

        #pragma unroll
        for (int l = 0; l < 16; l++) {
            int idx = tid + l * 256;
            int r = idx >> 6;
            int n = idx & 63;
            Csh[n][r] = aux[(size_t)(t0 + r) * AUX_W + 96 + n];
            Bsh[n][r] = aux[(size_t)(s0 + r) * AUX_W + 32 + n];
        }
        __syncthreads();

        int ty = tid / 16, tx = tid % 16;
        int r0 = ty * 4, c0 = tx * 4;
        float acc[4][4];
        #pragma unroll
        for (int i = 0; i < 4; i++)
            #pragma unroll
            for (int j = 0; j < 4; j++) acc[i][j] = 0.f;

        #pragma unroll
        for (int k = 0; k < D_STATE; k++) {
            float ra[4], rb[4];
            #pragma unroll
            for (int i = 0; i < 4; i++) ra[i] = Csh[k][r0 + i];
            #pragma unroll
            for (int j = 0; j < 4; j++) rb[j] = Bsh[k][c0 + j];
            #pragma unroll
            for (int i = 0; i < 4; i++)
                #pragma unroll
                for (int j = 0; j < 4; j++) acc[i][j] += ra[i] * rb[j];
        }
        #pragma unroll
        for (int i = 0; i < 4; i++)
            #pragma unroll
            for (int j = 0; j < 4; j++) {
                int tt = t0 + r0 + i, ssd = s0 + c0 + j;
                Gm[(size_t)tt * SEQ + ssd] =
                    (ssd <= tt) ? __float2bfloat16(acc[i][j])
                                : __float2bfloat16(0.f);
            }
    }
}

// ---------------- SSM attention: split-s double-tile pipelined WMMA ------
// Grid (8, 32, 2): CTA z handles double-tiles d in {z, z+2} (< ND).
// Per-(ti) reference r = la[t0]; partials (bf16) summable across z.
#define TILE_E (64 * 72)
#define ATTN_SMEM (2 * 4 * TILE_E * 2)   // 73728

__global__ void __launch_bounds__(256)
attn_kernel(const __nv_bfloat16* __restrict__ Gm,
            const __nv_bfloat16* __restrict__ hb,
            const float* __restrict__ la,
            const float* __restrict__ dt,
            __nv_bfloat16* __restrict__ ypart) {
    extern __shared__ char dsm8[];
    __nv_bfloat16* Gs = (__nv_bfloat16*)dsm8;
    __nv_bfloat16* Xs = (__nv_bfloat16*)dsm8 + 4 * TILE_E;
    float* Ys = (float*)dsm8;

    __shared__ __nv_bfloat162 es2[256];
    __shared__ float          etf[64];

    const int bidx = blockIdx.x;
    const int ti   = (bidx < 4) ? bidx : 11 - bidx;
    const int head = blockIdx.y;
    const int zz   = blockIdx.z;
    const int t0   = ti * 64;
    const int tid  = threadIdx.x;
    const int wid  = tid >> 5;
    const int wy   = wid >> 1;
    const int wx   = wid & 1;

    const float* laH = la + head * SEQ;
    const float* dtH = dt + head * SEQ;
    const int NT = ti + 1;
    const int ND = (NT + 1) >> 1;
    const int smax = t0 + 63;

    int dlist[2];
    int nd = 0;
    for (int d = zz; d < ND; d += 2) dlist[nd++] = d;

    {
        float la_r = laH[t0];
        for (int i = tid; i < ND * 64; i += 256) {
            int s = 2 * i;
            float a0 = (s     <= smax) ? __expf(la_r - laH[s])     * dtH[s]     : 0.f;
            float a1 = (s + 1 <= smax) ? __expf(la_r - laH[s + 1]) * dtH[s + 1] : 0.f;
            es2[i] = __floats2bfloat162_rn(a0, a1);
        }
        if (tid < 64)
            etf[tid] = __expf(laH[t0 + tid] - la_r);
    }

    auto issue = [&](int d, int sb) {
        int s0 = d * 128;
        #pragma unroll
        for (int l = 0; l < 4; l++) {
            int idx = tid + l * 256;
            int slot = sb + (idx >> 9);
            int r    = (idx >> 3) & 63;
            int c16  = (idx & 7) * 16;
            int scol = s0 + ((idx >> 9) << 6);
            cp_async16(smem_u32(Gs + slot * TILE_E + r * 72) + c16,
                       (const char*)(Gm + (size_t)(t0 + r) * SEQ + scol) + c16);
            cp_async16(smem_u32(Xs + slot * TILE_E + r * 72) + c16,
                       (const char*)(hb + (size_t)(scol + r) * D_INNER
                                        + head * HEAD_DIM) + c16);
        }
        cp_commit();
    };

    wmma::fragment<wmma::accumulator, 16, 16, 16, float> acc[2];
    wmma::fill_fragment(acc[0], 0.0f);
    wmma::fill_fragment(acc[1], 0.0f);

    if (nd > 0) issue(dlist[0], 0);
    if (nd > 1) issue(dlist[1], 2);

    for (int i = 0; i < nd; i++) {
        int d  = dlist[i];
        int sb = 2 * i;
        if (i + 1 < nd) cp_wait<1>(); else cp_wait<0>();
        __syncthreads();

        #pragma unroll
        for (int hh = 0; hh < 2; hh++) {
            __nv_bfloat16* Gb = Gs + (sb + hh) * TILE_E;
            const int esBase = d * 64 + hh * 32;
            #pragma unroll
            for (int l = 0; l < 4; l++) {
                int u   = tid + l * 256;
                int tl  = u >> 4;
                int sl4 = (u & 15) * 4;
                uint2* p = reinterpret_cast<uint2*>(Gb + tl * 72 + sl4);
                uint2 v = *p;
                __nv_bfloat162 g0 = *reinterpret_cast<__nv_bfloat162*>(&v.x);
                __nv_bfloat162 g1 = *reinterpret_cast<__nv_bfloat162*>(&v.y);
                g0 = __hmul2(g0, es2[esBase + (sl4 >> 1)]);
                g1 = __hmul2(g1, es2[esBase + (sl4 >> 1) + 1]);
                v.x = *reinterpret_cast<uint32_t*>(&g0);
                v.y = *reinterpret_cast<uint32_t*>(&g1);
                *p = v;
            }
        }
        __syncthreads();

        #pragma unroll
        for (int hh = 0; hh < 2; hh++) {
            __nv_bfloat16* Gb = Gs + (sb + hh) * TILE_E;
            __nv_bfloat16* Xb = Xs + (sb + hh) * TILE_E;
            #pragma unroll
            for (int ks = 0; ks < 4; ks++) {
                wmma::fragment<wmma::matrix_a, 16, 16, 16,
                               __nv_bfloat16, wmma::row_major> af;
                wmma::load_matrix_sync(af, Gb + (wy * 16) * 72 + ks * 16, 72);
                #pragma unroll
                for (int n = 0; n < 2; n++) {
                    wmma::fragment<wmma::matrix_b, 16, 16, 16,
                                   __nv_bfloat16, wmma::row_major> bf;
                    wmma::load_matrix_sync(bf,
                        Xb + (ks * 16) * 72 + wx * 32 + n * 16, 72);
                    wmma::mma_sync(acc[n], af, bf, acc[n]);
                }
            }
        }
    }

    __syncthreads();
    #pragma unroll
    for (int n = 0; n < 2; n++)
        wmma::store_matrix_sync(Ys + (wy * 16) * 68 + wx * 32 + n * 16, acc[n],
                                68, wmma::mem_row_major);
    __syncthreads();
    __nv_bfloat16* yz = ypart + (size_t)zz * SEQ * D_INNER;
    #pragma unroll
    for (int l = 0; l < 16; l++) {
        int idx = tid + l * 256;
        int row = idx >> 6, col = idx & 63;
        yz[(size_t)(t0 + row) * D_INNER + head * HEAD_DIM + col] =
            __float2bfloat16(Ys[row * 68 + col] * etf[row]);
    }
}

// ---------------- gate: yb = bf16((p0+p1) * silu(gate)) ----------------
__global__ void __launch_bounds__(256)
gate_kernel(const __nv_bfloat16* __restrict__ ypart,
            const __nv_bfloat16* __restrict__ projb,
            __nv_bfloat16* __restrict__ yb) {
    int i = blockIdx.x * blockDim.x + threadIdx.x;  // over SEQ*D_INNER/4
    int e = i * 4;
    int t = e >> 11;
    int c = e & (D_INNER - 1);
    uint2 u0 = reinterpret_cast<const uint2*>(ypart)[i];
    uint2 u1 = reinterpret_cast<const uint2*>(ypart + SEQ * D_INNER)[i];
    uint2 gp = *reinterpret_cast<const uint2*>(
        &projb[(size_t)t * PROJ + COL_GATE + c]);
    __nv_bfloat162 p0a = *reinterpret_cast<__nv_bfloat162*>(&u0.x);
    __nv_bfloat162 p0b = *reinterpret_cast<__nv_bfloat162*>(&u0.y);
    __nv_bfloat162 p1a = *reinterpret_cast<__nv_bfloat162*>(&u1.x);
    __nv_bfloat162 p1b = *reinterpret_cast<__nv_bfloat162*>(&u1.y);
    __nv_bfloat162 ga = *reinterpret_cast<__nv_bfloat162*>(&gp.x);
    __nv_bfloat162 gb = *reinterpret_cast<__nv_bfloat162*>(&gp.y);
    float y0 = (__bfloat162float(p0a.x) + __bfloat162float(p1a.x)) *
               siluf(__bfloat162float(ga.x));
    float y1 = (__bfloat162float(p0a.y) + __bfloat162float(p1a.y)) *
               siluf(__bfloat162float(ga.y));
    float y2 = (__bfloat162float(p0b.x) + __bfloat162float(p1b.x)) *
               siluf(__bfloat162float(gb.x));
    float y3 = (__bfloat162float(p0b.y) + __bfloat162float(p1b.y)) *
               siluf(__bfloat162float(gb.y));
    __nv_bfloat162 o0 = __floats2bfloat162_rn(y0, y1);
    __nv_bfloat162 o1 = __floats2bfloat162_rn(y2, y3);
    uint2 pk;
    pk.x = *reinterpret_cast<uint32_t*>(&o0);
    pk.y = *reinterpret_cast<uint32_t*>(&o1);
    *reinterpret_cast<uint2*>(&yb[e]) = pk;
}

// ---------------- combine: out = x + sum_{z<4} part_z ----------------
__global__ void combine_kernel(const float* __restrict__ x,
                               const float* __restrict__ part,
                               float* __restrict__ out) {
    int i = blockIdx.x * blockDim.x + threadIdx.x;   // SEQ*N_EMBD/4
    float4 a = reinterpret_cast<const float4*>(x)[i];
    #pragma unroll
    for (int z = 0; z < 4; z++) {
        float4 p = reinterpret_cast<const float4*>(part + (size_t)z * SEQ * N_EMBD)[i];
        a.x += p.x;  a.y += p.y;  a.z += p.z;  a.w += p.w;
    }
    reinterpret_cast<float4*>(out)[i] = a;
}

// ---------------- host launch ----------------
#define GEMM_SMEM (2 * 64 * 72 * 2 + 2 * 64 * 136 * 2)   // 53248

extern "C" void kernel_launch(void* const* d_in, const int* in_sizes, int n_in,
                              void* d_out, int out_size) {
    const float* x        = (const float*)d_in[0];
    const float* nscale   = (const float*)d_in[1];
    const float* w_in     = (const float*)d_in[2];
    const float* conv_w   = (const float*)d_in[3];
    const float* conv_b   = (const float*)d_in[4];
    const float* A_log    = (const float*)d_in[5];
    const float* dt_bias  = (const float*)d_in[6];
    const float* w_out    = (const float*)d_in[7];
    float* out = (float*)d_out;

    void *p_xnb, *p_projb, *p_aux, *p_hb, *p_dt, *p_la, *p_G, *p_part,
         *p_yp, *p_yb, *p_w1, *p_w2;
    cudaGetSymbolAddress(&p_xnb,   g_xnb);
    cudaGetSymbolAddress(&p_projb, g_projb);
    cudaGetSymbolAddress(&p_aux,   g_aux);
    cudaGetSymbolAddress(&p_hb,    g_hb);
    cudaGetSymbolAddress(&p_dt,    g_dt);
    cudaGetSymbolAddress(&p_la,    g_la);
    cudaGetSymbolAddress(&p_G,     g_Gb);
    cudaGetSymbolAddress(&p_part,  g_part);
    cudaGetSymbolAddress(&p_yp,    g_ypart);
    cudaGetSymbolAddress(&p_yb,    g_yb);
    cudaGetSymbolAddress(&p_w1,    g_w1b);
    cudaGetSymbolAddress(&p_w2,    g_w2b);
    __nv_bfloat16* xnb   = (__nv_bfloat16*)p_xnb;
    __nv_bfloat16* projb = (__nv_bfloat16*)p_projb;
    float*         aux   = (float*)p_aux;
    __nv_bfloat16* hb    = (__nv_bfloat16*)p_hb;
    float*         dt    = (float*)p_dt;
    float*         la    = (float*)p_la;
    __nv_bfloat16* Gmb   = (__nv_bfloat16*)p_G;
    float*         part  = (float*)p_part;
    __nv_bfloat16* ypart = (__nv_bfloat16*)p_yp;
    __nv_bfloat16* ybuf  = (__nv_bfloat16*)p_yb;
    __nv_bfloat16* w1b   = (__nv_bfloat16*)p_w1;
    __nv_bfloat16* w2b   = (__nv_bfloat16*)p_w2;

    cudaFuncSetAttribute(bf16_gemm_kernel<64, 128, 2, 4, 1>,
        cudaFuncAttributeMaxDynamicSharedMemorySize, GEMM_SMEM);
    cudaFuncSetAttribute(bf16_gemm_kernel<64, 128, 2, 4, 0>,
        cudaFuncAttributeMaxDynamicSharedMemorySize, GEMM_SMEM);
    cudaFuncSetAttribute(attn_kernel,
        cudaFuncAttributeMaxDynamicSharedMemorySize, ATTN_SMEM);

    // prologue: weight casts + rmsnorm (one launch)
    prologue_kernel<<<W1_BLKS + W2_BLKS + SEQ, 256>>>(
        w_in, w_out, x, nscale, w1b, w2b, xnb);

    // GEMM1: projb/aux = xn @ w_in   (bf16 + fp32 aux epilogue)
    {
        dim3 grid((PROJ + 127) / 128, SEQ / 64, 1);
        bf16_gemm_kernel<64, 128, 2, 4, 1><<<grid, 256, GEMM_SMEM>>>(
            xnb, w1b, nullptr, projb, aux, SEQ, PROJ, N_EMBD, N_EMBD);
    }

    // mid: conv + dt scan + masked bf16 cbt (one launch)
    mid_kernel<<<CONV_BLKS + DT_BLKS + CBT_BLKS, 256>>>(
        projb, aux, conv_w, conv_b, dt_bias, A_log, hb, dt, la, Gmb);

    // attn split-s: 512 CTAs, bf16 partials
    attn_kernel<<<dim3(SEQ / 64, N_HEADS, 2), 256, ATTN_SMEM>>>(
        Gmb, hb, la, dt, ypart);

    // gate: yb = bf16((p0+p1) * silu(gate))
    gate_kernel<<<(SEQ * D_INNER / 4) / 256, 256>>>(ypart, projb, ybuf);

    // GEMM2 (split-K=4): part[z] = yb[:, z*512:(z+1)*512] @ w_out[z...]
    {
        dim3 grid(N_EMBD / 128, SEQ / 64, 4);          // 8 x 8 x 4 = 256 CTAs
        bf16_gemm_kernel<64, 128, 2, 4, 0><<<grid, 256, GEMM_SMEM>>>(
            ybuf, w2b, part, nullptr, nullptr, SEQ, N_EMBD, D_INNER, D_INNER / 4);
    }

    combine_kernel<<<(SEQ * N_EMBD / 4) / 256, 256>>>(x, part, out);
}